// round 1
// baseline (speedup 1.0000x reference)
#include <cuda_runtime.h>
#include <cstdint>

#define NA 76725
#define NC 80
#define CA (NA * NC)           // 6,138,000
#define MAXK 200
#define CAND 2048
#define CHUNK 512
#define NMS_NT 512

// -------- device scratch (no allocations allowed) --------
__device__ float g_boxes[NA * 4];
__device__ float g_areas[NA];
__device__ float g_scoresT[(size_t)NC * NA];   // transposed classification [C, A]

// -------- kernel 1: fill defaults --------
// layout (float32): [0,CA) scores=0 ; [CA,2CA) labels=-1 ; [2CA,6CA) boxes=0 ; [6CA,7CA) keep=0
__global__ void k_fill(float4* __restrict__ out4, int n4) {
    int i = blockIdx.x * blockDim.x + threadIdx.x;
    const int lo = CA / 4;       // start of label region in float4 units
    const int hi = (2 * CA) / 4; // end of label region
    if (i < n4) {
        float v = (i >= lo && i < hi) ? -1.0f : 0.0f;
        out4[i] = make_float4(v, v, v, v);
    }
}

// -------- kernel 2: decode + clip boxes, compute areas --------
__global__ void k_decode(const float4* __restrict__ reg, const float4* __restrict__ anc) {
    int i = blockIdx.x * blockDim.x + threadIdx.x;
    if (i >= NA) return;
    float4 a = anc[i];
    float4 r = reg[i];
    float aw = a.z - a.x;
    float ah = a.w - a.y;
    float ax = a.x + 0.5f * aw;
    float ay = a.y + 0.5f * ah;
    float cx = ax + r.x * 0.1f * aw;
    float cy = ay + r.y * 0.1f * ah;
    float w = aw * expf(r.z * 0.2f);
    float h = ah * expf(r.w * 0.2f);
    float x1 = fminf(fmaxf(cx - 0.5f * w, 0.0f), 640.0f);
    float y1 = fminf(fmaxf(cy - 0.5f * h, 0.0f), 640.0f);
    float x2 = fminf(fmaxf(cx + 0.5f * w, 0.0f), 640.0f);
    float y2 = fminf(fmaxf(cy + 0.5f * h, 0.0f), 640.0f);
    reinterpret_cast<float4*>(g_boxes)[i] = make_float4(x1, y1, x2, y2);
    g_areas[i] = (x2 - x1) * (y2 - y1);
}

// -------- kernel 3: transpose classification [A,80] -> [80,A] --------
__global__ void k_transpose(const float* __restrict__ cls) {
    __shared__ float tile[32 * 81];
    int a0 = blockIdx.x * 32;
    int tid = threadIdx.x;
    // coalesced load: 32 anchors x 80 classes contiguous
    for (int t = tid; t < 32 * 80; t += 256) {
        size_t g = (size_t)a0 * 80 + t;
        if (g < (size_t)NA * 80) {
            int ai = t / 80;
            int c = t - ai * 80;
            tile[ai * 81 + c] = cls[g];
        }
    }
    __syncthreads();
    // coalesced store: consecutive anchors for fixed class
    for (int t = tid; t < 32 * 80; t += 256) {
        int c = t >> 5;
        int ai = t & 31;
        int a = a0 + ai;
        if (a < NA) g_scoresT[(size_t)c * NA + a] = tile[ai * 81 + c];
    }
}

// -------- kernel 4: per-class NMS (one CTA per class) --------
struct SmemT {
    unsigned long long keys[CAND];   // (~score_bits)<<32 | idx : ascending sort = desc score, asc idx
    float4 cbox[CHUNK];
    float  carea[CHUNK];
    float4 kbox[MAXK];
    float  karea[MAXK];
    int    kidx[MAXK];
    float  kscore[MAXK];
    int    hist[1024];
    int    cnt;
    int    keptn;
};

__global__ void __launch_bounds__(NMS_NT) k_nms(float* __restrict__ out) {
    __shared__ SmemT sm;
    const int c = blockIdx.x;
    const int tid = threadIdx.x;
    const float* sc = g_scoresT + (size_t)c * NA;

    // ---- phase 0: histogram of scores > 0.1 ----
    for (int i = tid; i < 1024; i += NMS_NT) sm.hist[i] = 0;
    if (tid == 0) { sm.keptn = 0; }
    __syncthreads();
    for (int j = tid; j < NA; j += NMS_NT) {
        float s = sc[j];
        if (s > 0.1f) {
            int b = (int)(s * 1024.0f);
            if (b > 1023) b = 1023;
            atomicAdd(&sm.hist[b], 1);
        }
    }
    __syncthreads();

    // ---- phase 1: tranche loop (usually a single tranche) ----
    int curHi = 1023;
    bool exhausted = false;
    while (true) {
        __syncthreads();
        if (sm.keptn >= MAXK) break;

        // pick bucket range [lo+1, curHi] with total count <= CAND (whole buckets)
        int cnt = 0;
        int lo = curHi;
        while (lo >= 0) {
            int h = sm.hist[lo];
            if (cnt > 0 && cnt + h > CAND) break;
            cnt += h;
            lo--;
        }
        if (cnt == 0) { exhausted = true; break; }  // candidate pool fully consumed

        // selection pass
        if (tid == 0) sm.cnt = 0;
        __syncthreads();
        for (int j = tid; j < NA; j += NMS_NT) {
            float s = sc[j];
            if (s > 0.1f) {
                int b = (int)(s * 1024.0f);
                if (b > 1023) b = 1023;
                if (b > lo && b <= curHi) {
                    int p = atomicAdd(&sm.cnt, 1);
                    if (p < CAND) {
                        unsigned sb = ~__float_as_uint(s);
                        sm.keys[p] = ((unsigned long long)sb << 32) | (unsigned)j;
                    }
                }
            }
        }
        __syncthreads();
        int n_tr = sm.cnt;
        if (n_tr > CAND) n_tr = CAND;
        for (int i = n_tr + tid; i < CAND; i += NMS_NT)
            sm.keys[i] = 0xFFFFFFFFFFFFFFFFULL;
        __syncthreads();

        // bitonic sort (ascending u64 => descending score, ascending index)
        for (int k = 2; k <= CAND; k <<= 1) {
            for (int j = k >> 1; j > 0; j >>= 1) {
                for (int i = tid; i < CAND; i += NMS_NT) {
                    int ixj = i ^ j;
                    if (ixj > i) {
                        unsigned long long va = sm.keys[i];
                        unsigned long long vb = sm.keys[ixj];
                        bool up = ((i & k) == 0);
                        if ((va > vb) == up) { sm.keys[i] = vb; sm.keys[ixj] = va; }
                    }
                }
                __syncthreads();
            }
        }

        // greedy walk, chunked with smem-prefetched boxes
        int pos = 0;
        while (pos < n_tr && sm.keptn < MAXK) {
            int chunkN = n_tr - pos;
            if (chunkN > CHUNK) chunkN = CHUNK;
            for (int t = tid; t < chunkN; t += NMS_NT) {
                unsigned long long key = sm.keys[pos + t];
                int idx = (int)(unsigned)(key & 0xFFFFFFFFULL);
                sm.cbox[t] = reinterpret_cast<const float4*>(g_boxes)[idx];
                sm.carea[t] = g_areas[idx];
            }
            __syncthreads();
            if (tid < 32) {
                int kn = sm.keptn;
                for (int t = 0; t < chunkN && kn < MAXK; t++) {
                    float4 cb = sm.cbox[t];
                    float car = sm.carea[t];
                    bool sup = false;
                    for (int k = tid; k < kn; k += 32) {
                        float4 kb = sm.kbox[k];
                        float ix1 = fmaxf(cb.x, kb.x);
                        float iy1 = fmaxf(cb.y, kb.y);
                        float ix2 = fminf(cb.z, kb.z);
                        float iy2 = fminf(cb.w, kb.w);
                        float iw = fmaxf(ix2 - ix1, 0.0f);
                        float ih = fmaxf(iy2 - iy1, 0.0f);
                        float inter = iw * ih;
                        float iou = inter / (sm.karea[k] + car - inter);
                        if (iou > 0.5f) sup = true;
                    }
                    if (__ballot_sync(0xFFFFFFFFu, sup) == 0u) {
                        if (tid == 0) {
                            unsigned long long key = sm.keys[pos + t];
                            sm.kbox[kn] = cb;
                            sm.karea[kn] = car;
                            sm.kidx[kn] = (int)(unsigned)(key & 0xFFFFFFFFULL);
                            sm.kscore[kn] = __uint_as_float(~(unsigned)(key >> 32));
                        }
                        kn++;
                        __syncwarp();
                    }
                }
                if (tid == 0) sm.keptn = kn;
            }
            __syncthreads();
            pos += chunkN;
        }
        curHi = lo;
    }
    __syncthreads();

    // ---- phase 2: scatter kept detections ----
    // Reference quirk: if the candidate pool exhausts before MAX_DET iterations,
    // the remaining argmax(all -1) iterations force keep[0] = False.
    int kn = sm.keptn;
    for (int t = tid; t < kn; t += NMS_NT) {
        int a = sm.kidx[t];
        if (exhausted && a == 0) continue;
        size_t o = (size_t)c * NA + a;
        out[o] = sm.kscore[t];                                 // scores
        out[(size_t)CA + o] = (float)c;                        // labels
        reinterpret_cast<float4*>(out + 2 * (size_t)CA)[o] = sm.kbox[t];  // boxes
        out[6 * (size_t)CA + o] = 1.0f;                        // keep
    }
}

// -------- launcher --------
extern "C" void kernel_launch(void* const* d_in, const int* in_sizes, int n_in,
                              void* d_out, int out_size) {
    const float* cls = (const float*)d_in[0];       // [1, A, 80]
    const float4* reg = (const float4*)d_in[1];     // [1, A, 4]
    const float4* anc = (const float4*)d_in[2];     // [A, 4]
    float* out = (float*)d_out;

    int n4 = out_size / 4;
    k_fill<<<(n4 + 255) / 256, 256>>>((float4*)d_out, n4);
    k_decode<<<(NA + 255) / 256, 256>>>(reg, anc);
    k_transpose<<<(NA + 31) / 32, 256>>>(cls);
    k_nms<<<NC, NMS_NT>>>(out);
}

// round 2
// speedup vs baseline: 2.3093x; 2.3093x over previous
#include <cuda_runtime.h>
#include <cstdint>

#define NA 76725
#define NC 80
#define CA (NA * NC)           // 6,138,000
#define MAXK 200
#define CAND 2048
#define NT 1024

// -------- device scratch (no allocations allowed) --------
__device__ float g_boxes[NA * 4];
__device__ float g_areas[NA];
__device__ float g_scoresT[(size_t)NC * NA];   // transposed classification [C, A]

// -------- kernel: decode + clip boxes, compute areas --------
__global__ void k_decode(const float4* __restrict__ reg, const float4* __restrict__ anc) {
    int i = blockIdx.x * blockDim.x + threadIdx.x;
    if (i >= NA) return;
    float4 a = anc[i];
    float4 r = reg[i];
    float aw = a.z - a.x;
    float ah = a.w - a.y;
    float ax = a.x + 0.5f * aw;
    float ay = a.y + 0.5f * ah;
    float cx = ax + r.x * 0.1f * aw;
    float cy = ay + r.y * 0.1f * ah;
    float w = aw * expf(r.z * 0.2f);
    float h = ah * expf(r.w * 0.2f);
    float x1 = fminf(fmaxf(cx - 0.5f * w, 0.0f), 640.0f);
    float y1 = fminf(fmaxf(cy - 0.5f * h, 0.0f), 640.0f);
    float x2 = fminf(fmaxf(cx + 0.5f * w, 0.0f), 640.0f);
    float y2 = fminf(fmaxf(cy + 0.5f * h, 0.0f), 640.0f);
    reinterpret_cast<float4*>(g_boxes)[i] = make_float4(x1, y1, x2, y2);
    g_areas[i] = (x2 - x1) * (y2 - y1);
}

// -------- kernel: transpose classification [A,80] -> [80,A] --------
__global__ void k_transpose(const float* __restrict__ cls) {
    __shared__ float tile[32 * 81];
    int a0 = blockIdx.x * 32;
    int tid = threadIdx.x;
    for (int t = tid; t < 32 * 80; t += 256) {
        size_t g = (size_t)a0 * 80 + t;
        if (g < (size_t)NA * 80) {
            int ai = t / 80;
            int c = t - ai * 80;
            tile[ai * 81 + c] = cls[g];
        }
    }
    __syncthreads();
    for (int t = tid; t < 32 * 80; t += 256) {
        int c = t >> 5;
        int ai = t & 31;
        int a = a0 + ai;
        if (a < NA) g_scoresT[(size_t)c * NA + a] = tile[ai * 81 + c];
    }
}

// -------- per-class NMS smem layout --------
struct SmemT {
    float4 cbox[CAND];               // 32 KB  (sorted candidate boxes)
    float4 kbox[MAXK];               // 3.2 KB
    unsigned long long keys[CAND];   // 16 KB : (~score_bits)<<32 | idx
    float  carea[CAND];              // 8 KB
    float  karea[MAXK];
    float  kscore[MAXK];
    int    kidx[MAXK];
    int    hist[1024];               // 4 KB
    unsigned mask[32];               // intra-batch suppression rows
    unsigned ph1bits;                // batch vs confirmed-kept suppression
    unsigned keepbits;
    int    cnt;
    int    kn;
    int    kn_new;
};

__global__ void __launch_bounds__(NT) k_nms(float* __restrict__ out) {
    extern __shared__ char smem_raw[];
    SmemT& sm = *reinterpret_cast<SmemT*>(smem_raw);
    const int c = blockIdx.x;
    const int tid = threadIdx.x;
    const int wid = tid >> 5;
    const int lane = tid & 31;
    const float* sc = g_scoresT + (size_t)c * NA;

    // ---- phase A: fill this class's output rows with defaults (overlaps with later compute) ----
    {
        size_t rs = (size_t)c * NA;
        float4 z4 = make_float4(0.f, 0.f, 0.f, 0.f);
        float4* ob = reinterpret_cast<float4*>(out + 2 * (size_t)CA) + rs;
        for (int i = tid; i < NA; i += NT) {
            out[rs + i] = 0.0f;                    // scores
            out[(size_t)CA + rs + i] = -1.0f;      // labels
            out[6 * (size_t)CA + rs + i] = 0.0f;   // keep
            ob[i] = z4;                            // boxes
        }
    }

    // ---- phase B: histogram of scores > 0.1 ----
    for (int i = tid; i < 1024; i += NT) sm.hist[i] = 0;
    if (tid == 0) sm.kn = 0;
    __syncthreads();
    for (int j = tid; j < NA; j += NT) {
        float s = sc[j];
        if (s > 0.1f) {
            int b = (int)(s * 1024.0f);
            if (b > 1023) b = 1023;
            atomicAdd(&sm.hist[b], 1);
        }
    }
    __syncthreads();

    // ---- phase C: tranche loop (usually one tranche) ----
    int curHi = 1023;
    bool exhausted = false;
    while (true) {
        // all threads compute identical bucket range [lo+1, curHi], total <= CAND (whole buckets)
        int cnt = 0, lo = curHi;
        while (lo >= 0) {
            int h = sm.hist[lo];
            if (cnt > 0 && cnt + h > CAND) break;
            cnt += h;
            lo--;
        }
        if (cnt == 0) { exhausted = true; break; }   // pool fully consumed

        // selection pass
        if (tid == 0) sm.cnt = 0;
        __syncthreads();
        for (int j = tid; j < NA; j += NT) {
            float s = sc[j];
            if (s > 0.1f) {
                int b = (int)(s * 1024.0f);
                if (b > 1023) b = 1023;
                if (b > lo && b <= curHi) {
                    int p = atomicAdd(&sm.cnt, 1);
                    if (p < CAND) {
                        unsigned sb = ~__float_as_uint(s);
                        sm.keys[p] = ((unsigned long long)sb << 32) | (unsigned)j;
                    }
                }
            }
        }
        __syncthreads();
        int n_tr = sm.cnt;
        if (n_tr > CAND) n_tr = CAND;
        for (int i = n_tr + tid; i < CAND; i += NT)
            sm.keys[i] = 0xFFFFFFFFFFFFFFFFULL;
        __syncthreads();

        // bitonic sort (ascending u64 => descending score, ascending index = JAX argmax order)
        for (int k = 2; k <= CAND; k <<= 1) {
            for (int j = k >> 1; j > 0; j >>= 1) {
                for (int i = tid; i < CAND; i += NT) {
                    int ixj = i ^ j;
                    if (ixj > i) {
                        unsigned long long va = sm.keys[i];
                        unsigned long long vb = sm.keys[ixj];
                        bool up = ((i & k) == 0);
                        if ((va > vb) == up) { sm.keys[i] = vb; sm.keys[ixj] = va; }
                    }
                }
                __syncthreads();
            }
        }

        // gather candidate boxes/areas in sorted order
        for (int t = tid; t < n_tr; t += NT) {
            int idx = (int)(unsigned)(sm.keys[t] & 0xFFFFFFFFULL);
            sm.cbox[t] = reinterpret_cast<const float4*>(g_boxes)[idx];
            sm.carea[t] = g_areas[idx];
        }
        __syncthreads();

        // ---- batched speculative greedy: 32 candidates per batch ----
        int pos = 0;
        while (pos < n_tr && sm.kn < MAXK) {
            int bn = n_tr - pos;
            if (bn > 32) bn = 32;
            if (tid == 0) sm.ph1bits = 0;
            __syncthreads();
            int kn0 = sm.kn;

            // phase 1: warp w checks candidate (pos+w) vs confirmed kept list
            if (wid < bn) {
                float4 cb = sm.cbox[pos + wid];
                float car = sm.carea[pos + wid];
                bool sup = false;
                for (int k = lane; k < kn0; k += 32) {
                    float4 kb = sm.kbox[k];
                    float ix1 = fmaxf(cb.x, kb.x);
                    float iy1 = fmaxf(cb.y, kb.y);
                    float ix2 = fminf(cb.z, kb.z);
                    float iy2 = fminf(cb.w, kb.w);
                    float inter = fmaxf(ix2 - ix1, 0.0f) * fmaxf(iy2 - iy1, 0.0f);
                    float iou = inter / (sm.karea[k] + car - inter);
                    if (iou > 0.5f) sup = true;
                }
                unsigned b = __ballot_sync(0xFFFFFFFFu, sup);
                if (lane == 0 && b) atomicOr(&sm.ph1bits, 1u << wid);
            }

            // phase 2: intra-batch pairwise IoU matrix (warp w = row w, lane = col)
            {
                bool hit = false;
                if (wid < bn && lane < bn && lane > wid) {
                    float4 wb = sm.cbox[pos + wid];     // earlier candidate (acts as kept box)
                    float4 jb = sm.cbox[pos + lane];    // later candidate
                    float ix1 = fmaxf(wb.x, jb.x);
                    float iy1 = fmaxf(wb.y, jb.y);
                    float ix2 = fminf(wb.z, jb.z);
                    float iy2 = fminf(wb.w, jb.w);
                    float inter = fmaxf(ix2 - ix1, 0.0f) * fmaxf(iy2 - iy1, 0.0f);
                    float iou = inter / (sm.carea[pos + wid] + sm.carea[pos + lane] - inter);
                    hit = iou > 0.5f;
                }
                unsigned m = __ballot_sync(0xFFFFFFFFu, hit);
                if (lane == 0 && wid < bn) sm.mask[wid] = m;
            }
            __syncthreads();

            // serial resolve (pure bit ops, ~bn iterations)
            if (tid == 0) {
                unsigned S = sm.ph1bits;
                unsigned keep = 0;
                int knl = sm.kn;
                for (int i = 0; i < bn; i++) {
                    if (knl >= MAXK) break;
                    if (!((S >> i) & 1u)) {
                        keep |= 1u << i;
                        knl++;
                        S |= sm.mask[i];
                    }
                }
                sm.keepbits = keep;
                sm.kn_new = knl;
            }
            __syncthreads();

            // parallel record of this batch's keeps
            unsigned keep = sm.keepbits;
            if (tid < 32 && ((keep >> tid) & 1u)) {
                int slot = kn0 + __popc(keep & ((1u << tid) - 1u));
                unsigned long long key = sm.keys[pos + tid];
                sm.kbox[slot] = sm.cbox[pos + tid];
                sm.karea[slot] = sm.carea[pos + tid];
                sm.kidx[slot] = (int)(unsigned)(key & 0xFFFFFFFFULL);
                sm.kscore[slot] = __uint_as_float(~(unsigned)(key >> 32));
            }
            __syncthreads();
            if (tid == 0) sm.kn = sm.kn_new;
            __syncthreads();
            pos += bn;
        }

        if (sm.kn >= MAXK) break;
        curHi = lo;
    }
    __syncthreads();

    // ---- phase D: scatter kept detections ----
    // Reference quirk: if the pool exhausts before MAX_DET iterations, the trailing
    // argmax(all -1) iterations overwrite keep[0] = False.
    int kn = sm.kn;
    for (int t = tid; t < kn; t += NT) {
        int a = sm.kidx[t];
        if (exhausted && a == 0) continue;
        size_t o = (size_t)c * NA + a;
        out[o] = sm.kscore[t];                                             // scores
        out[(size_t)CA + o] = (float)c;                                    // labels
        reinterpret_cast<float4*>(out + 2 * (size_t)CA)[o] = sm.kbox[t];   // boxes
        out[6 * (size_t)CA + o] = 1.0f;                                    // keep
    }
}

// -------- launcher --------
extern "C" void kernel_launch(void* const* d_in, const int* in_sizes, int n_in,
                              void* d_out, int out_size) {
    const float* cls = (const float*)d_in[0];       // [1, A, 80]
    const float4* reg = (const float4*)d_in[1];     // [1, A, 4]
    const float4* anc = (const float4*)d_in[2];     // [A, 4]
    float* out = (float*)d_out;

    cudaFuncSetAttribute(k_nms, cudaFuncAttributeMaxDynamicSharedMemorySize,
                         (int)sizeof(SmemT));

    k_decode<<<(NA + 255) / 256, 256>>>(reg, anc);
    k_transpose<<<(NA + 31) / 32, 256>>>(cls);
    k_nms<<<NC, NT, sizeof(SmemT)>>>(out);
}